// round 15
// baseline (speedup 1.0000x reference)
#include <cuda_runtime.h>

#define NPTS  4096
#define NB    8
#define CDIM  32
#define KOUT  9
#define KALL  18
#define TILE  128
#define NTHREADS 512

// shared memory layout (float offsets)
#define SM_QT 0
#define SM_PT (SM_QT + CDIM*TILE)            // 4096   pt[2][32][128]
#define SM_RN (SM_PT + 2*CDIM*TILE)          // 12288
#define SM_CN (SM_RN + TILE)                 // 12416  cn[2][128]
#define SM_QR (SM_CN + 2*TILE)               // 12672  qh_row[128]
#define SM_CT (SM_QR + TILE)                 // 12800  cnt_row[128] (int)
#define SM_BD (SM_CT + TILE)                 // 12928  survivor dists [128][128]
#define SM_BI (SM_BD + TILE*TILE)            // 29312  survivor idx (short) [128][128]
#define SMEM_FLOATS (SM_BI + (TILE*TILE)/2)  // 37504
#define SMEM_BYTES  (SMEM_FLOATS * 4)        // 150,016 bytes

__device__ float g_sq[NB * NPTS];

__global__ void sqnorm_kernel(const float* __restrict__ x) {
    int idx = blockIdx.x * blockDim.x + threadIdx.x;
    if (idx >= NB * NPTS) return;
    int b = idx >> 12;
    int n = idx & (NPTS - 1);
    const float* p = x + (size_t)(b * CDIM) * NPTS + n;
    float s = 0.f;
#pragma unroll
    for (int c = 0; c < CDIM; c++) {
        float v = p[c * NPTS];
        s = fmaf(v, v, s);
    }
    g_sq[idx] = s;
}

__device__ __forceinline__ void ffma2(unsigned long long& acc,
                                      unsigned long long a,
                                      unsigned long long b) {
    asm("fma.rn.f32x2 %0, %1, %2, %0;" : "+l"(acc) : "l"(a), "l"(b));
}
__device__ __forceinline__ unsigned long long packdup(float v) {
    unsigned long long r;
    asm("mov.b64 %0, {%1, %1};" : "=l"(r) : "r"(__float_as_uint(v)));
    return r;
}
__device__ __forceinline__ void unpack2(unsigned long long v, float& lo, float& hi) {
    unsigned int a, b;
    asm("mov.b64 {%0, %1}, %2;" : "=r"(a), "=r"(b) : "l"(v));
    lo = __uint_as_float(a); hi = __uint_as_float(b);
}

// lexicographic (d, idx) less-than == jax top_k order
#define LEX_LT(d1, i1, d2, i2) ((d1) < (d2) || ((d1) == (d2) && (i1) < (i2)))

// ---------------------------------------------------------------------------
// 128x128 tiles, 512 threads, FUSED epilogue filter (no dt roundtrip):
//  - compute: 32x16 grid, 4x4 f32x2 fragments (R13 mainloop, bit-identical)
//  - epilogue: d = (rn-2a)+cn in registers; d <= qh_row[r] -> ballot-compacted
//    push into per-row smem buffer (warp w's rows 8w..8w+7 are produced AND
//    consumed by warp w -> no atomics, no block barrier)
//  - phase B: 4 lanes per row take survivors k==q (mod 4); LEX (d,idx)
//    insert network (order-independent); row bound = shfl-min of lane 18ths
//  - pt/cn double-buffered: one __syncthreads per tile
//  - end: 4-way lexicographic merge per row
// ---------------------------------------------------------------------------
__global__ __launch_bounds__(NTHREADS, 1)
void knn_kernel(const float* __restrict__ x, float* __restrict__ out) {
    extern __shared__ float sm[];
    float* qt  = sm + SM_QT;
    float* ptb = sm + SM_PT;    // [2][32][128]
    float* rn  = sm + SM_RN;
    float* cnb = sm + SM_CN;    // [2][128]
    float* qhr = sm + SM_QR;    // per-row bound
    int*   ctr = (int*)(sm + SM_CT);
    float* bd  = sm + SM_BD;    // [row][slot]
    short* bi  = (short*)(sm + SM_BI);

    const int b    = blockIdx.y;
    const int row0 = blockIdx.x * TILE;
    const int tid  = threadIdx.x;
    const int tx   = tid & 15;
    const int ty   = tid >> 4;
    const int lane = tid & 31;
    const float* xb = x + (size_t)(b * CDIM) * NPTS;

    const int srow = tid >> 2;          // phase-B row (0..127)
    const int q4   = tid & 3;

    const unsigned halfmask = (tid & 16) ? 0xFFFF0000u : 0x0000FFFFu;
    const unsigned ltmask   = (1u << lane) - 1u;

    float dl[KALL];
    int   il[KALL];
#pragma unroll
    for (int j = 0; j < KALL; j++) { dl[j] = 3.4e38f; il[j] = 0x7FFFFFFF; }

#pragma unroll
    for (int k = 0; k < (CDIM * TILE) / NTHREADS; k++) {
        int idx = k * NTHREADS + tid;
        qt[idx] = xb[(idx >> 7) * NPTS + row0 + (idx & 127)];
    }
    if (tid < TILE) {
        rn[tid] = g_sq[b * NPTS + row0 + tid];
        qhr[tid] = 3.4e38f;
    }
    // prologue: tile 0 into buffer 0
#pragma unroll
    for (int k = 0; k < (CDIM * TILE) / NTHREADS; k++) {
        int idx = k * NTHREADS + tid;
        ptb[idx] = xb[(idx >> 7) * NPTS + (idx & 127)];
    }
    if (tid < TILE) cnb[tid] = g_sq[b * NPTS + tid];
    __syncthreads();

    for (int t = 0; t < NPTS / TILE; t++) {
        const int cur = t & 1;
        float* pt = ptb + cur * CDIM * TILE;
        float* cn = cnb + cur * TILE;
        const int m0 = t * TILE;

        // issue next tile's loads (hidden behind compute)
        if (t < NPTS / TILE - 1) {
            float* ptn = ptb + (cur ^ 1) * CDIM * TILE;
            int m1 = m0 + TILE;
#pragma unroll
            for (int k = 0; k < (CDIM * TILE) / NTHREADS; k++) {
                int idx = k * NTHREADS + tid;
                ptn[idx] = xb[(idx >> 7) * NPTS + m1 + (idx & 127)];
            }
            if (tid < TILE) cnb[(cur ^ 1) * TILE + tid] = g_sq[b * NPTS + m1 + tid];
        }

        // ---- 128x128x32 inner products: 4 rows x 4 col-pairs of f32x2 ----
        unsigned long long acc2[4][4];
#pragma unroll
        for (int i = 0; i < 4; i++)
#pragma unroll
            for (int j = 0; j < 4; j++) acc2[i][j] = 0ull;

#pragma unroll 2
        for (int c = 0; c < CDIM; c++) {
            float4 q = *(const float4*)(qt + c * TILE + 4 * ty);
            ulonglong2 pA = *(const ulonglong2*)(pt + c * TILE + 4 * tx);
            ulonglong2 pB = *(const ulonglong2*)(pt + c * TILE + 64 + 4 * tx);
            unsigned long long qq[4] = {packdup(q.x), packdup(q.y),
                                        packdup(q.z), packdup(q.w)};
#pragma unroll
            for (int i = 0; i < 4; i++) {
                ffma2(acc2[i][0], qq[i], pA.x);
                ffma2(acc2[i][1], qq[i], pA.y);
                ffma2(acc2[i][2], qq[i], pB.x);
                ffma2(acc2[i][3], qq[i], pB.y);
            }
        }

        // ---- fused epilogue + filter: ballot-compacted per-row push ----
        float cnv[8];
#pragma unroll
        for (int j = 0; j < 8; j++)
            cnv[j] = cn[(j < 4) ? (4 * tx + j) : (60 + 4 * tx + j)];

        int cnt[4] = {0, 0, 0, 0};
#pragma unroll
        for (int i = 0; i < 4; i++) {
            int r = 4 * ty + i;
            float rni = rn[r];
            float tvi = qhr[r];
            float a[8];
            unpack2(acc2[i][0], a[0], a[1]);
            unpack2(acc2[i][1], a[2], a[3]);
            unpack2(acc2[i][2], a[4], a[5]);
            unpack2(acc2[i][3], a[6], a[7]);
#pragma unroll
            for (int j = 0; j < 8; j++) {
                float d = (rni - 2.f * a[j]) + cnv[j];
                bool push = (d <= tvi);   // <= keeps boundary/tie candidates
                unsigned m = __ballot_sync(0xFFFFFFFFu, push);
                unsigned mh = m & halfmask;
                if (push) {
                    int pos = cnt[i] + __popc(mh & ltmask);
                    int col = (j < 4) ? (4 * tx + j) : (60 + 4 * tx + j);
                    bd[r * TILE + pos] = d;
                    bi[r * TILE + pos] = (short)(m0 + col);
                }
                cnt[i] += __popc(mh);
            }
        }
        if ((tid & 15) == 0) {   // lanes 0 and 16 publish their 4 rows' counts
#pragma unroll
            for (int i = 0; i < 4; i++) ctr[4 * ty + i] = cnt[i];
        }
        __syncwarp();

        // ---- phase B: 4 lanes per row, LEX insert (order-independent) ----
        {
            int c = ctr[srow];
            int mycnt = (c + 3 - q4) >> 2;           // entries q4, q4+4, ...
            int nmax = __reduce_max_sync(0xFFFFFFFFu, mycnt);
            for (int s = 0; s < nmax; s++) {
                float d  = 3.4e38f;
                int   mi = 0x7FFFFFFF;
                if (s < mycnt) {
                    int k = 4 * s + q4;
                    d  = bd[srow * TILE + k];
                    mi = (int)bi[srow * TILE + k];
                }
#pragma unroll
                for (int j = KALL - 1; j >= 1; j--) {
                    bool sh = LEX_LT(d, mi, dl[j - 1], il[j - 1]);
                    bool pl = !sh && LEX_LT(d, mi, dl[j], il[j]);
                    float pd = dl[j - 1]; int pi = il[j - 1];
                    dl[j] = sh ? pd : (pl ? d  : dl[j]);
                    il[j] = sh ? pi : (pl ? mi : il[j]);
                }
                if (LEX_LT(d, mi, dl[0], il[0])) { dl[0] = d; il[0] = mi; }
            }
            // row bound = min over the row's 4 lanes (consecutive lanes)
            float t18 = dl[KALL - 1];
            t18 = fminf(t18, __shfl_xor_sync(0xFFFFFFFFu, t18, 1));
            t18 = fminf(t18, __shfl_xor_sync(0xFFFFFFFFu, t18, 2));
            if (q4 == 0) qhr[srow] = t18;
        }
        __syncthreads();   // next-buffer loads visible; cur free to overwrite
    }

    // ---- dump lane lists into buffer region, then 4-way merge per row ----
    float* sd = bd;                       // 512*18 floats
    short* si = (short*)(bd + NTHREADS * KALL);
#pragma unroll
    for (int j = 0; j < KALL; j++) {
        sd[tid * KALL + j] = dl[j];
        si[tid * KALL + j] = (short)il[j];
    }
    __syncthreads();

    if (tid < TILE) {
        int cur4[4] = {0, 0, 0, 0};
        int n = row0 + tid;
        int base0 = (b * NPTS + n) * KOUT;
        int base1 = ((NB + b) * NPTS + n) * KOUT;
#pragma unroll
        for (int t = 0; t < KALL; t++) {
            float bdv = 3.5e38f;
            int   biv = 0x7FFFFFFF;
            int   bq = 0;
#pragma unroll
            for (int q = 0; q < 4; q++) {
                int c = cur4[q];
                float d2 = sd[(tid * 4 + q) * KALL + c];
                int   i2 = (int)si[(tid * 4 + q) * KALL + c];
                if (LEX_LT(d2, i2, bdv, biv)) { bdv = d2; biv = i2; bq = q; }
            }
            cur4[bq]++;
            if ((t & 1) == 0) out[base0 + (t >> 1)] = (float)biv;
        }
#pragma unroll
        for (int j = 0; j < KOUT; j++) out[base1 + j] = (float)n;
    }
}

extern "C" void kernel_launch(void* const* d_in, const int* in_sizes, int n_in,
                              void* d_out, int out_size) {
    const float* x = (const float*)d_in[0];
    float* out = (float*)d_out;

    cudaFuncSetAttribute(knn_kernel, cudaFuncAttributeMaxDynamicSharedMemorySize,
                         SMEM_BYTES);

    sqnorm_kernel<<<(NB * NPTS + 511) / 512, 512>>>(x);

    dim3 grid(NPTS / TILE, NB);
    knn_kernel<<<grid, NTHREADS, SMEM_BYTES>>>(x, out);
}

// round 16
// speedup vs baseline: 1.3184x; 1.3184x over previous
#include <cuda_runtime.h>

#define NPTS  4096
#define NB    8
#define CDIM  32
#define KOUT  9
#define KALL  18
#define TILE  128
#define NTHREADS 512
#define CAP   24

// shared memory layout (float offsets)
#define SM_QT (0)                            // qt2: duplicated u64 [32][128] = 8192 floats
#define SM_PT (SM_QT + 2*CDIM*TILE)          // 8192   pt[2][32][128]
#define SM_DT (SM_PT + 2*CDIM*TILE)          // 16384
#define SM_RN (SM_DT + TILE*TILE)            // 32768
#define SM_CN (SM_RN + TILE)                 // 32896  cn[2][128]
#define SM_QH (SM_CN + 2*TILE)               // 33152
#define SM_BD (SM_QH + NTHREADS)             // 33664
#define SM_BI (SM_BD + CAP*NTHREADS)         // 45952
#define SMEM_FLOATS (SM_BI + (CAP*NTHREADS)/2)   // 52096
#define SMEM_BYTES  (SMEM_FLOATS * 4)        // 208,384 bytes

__device__ float g_sq[NB * NPTS];

__global__ void sqnorm_kernel(const float* __restrict__ x) {
    int idx = blockIdx.x * blockDim.x + threadIdx.x;
    if (idx >= NB * NPTS) return;
    int b = idx >> 12;
    int n = idx & (NPTS - 1);
    const float* p = x + (size_t)(b * CDIM) * NPTS + n;
    float s = 0.f;
#pragma unroll
    for (int c = 0; c < CDIM; c++) {
        float v = p[c * NPTS];
        s = fmaf(v, v, s);
    }
    g_sq[idx] = s;
}

__device__ __forceinline__ void ffma2(unsigned long long& acc,
                                      unsigned long long a,
                                      unsigned long long b) {
    asm("fma.rn.f32x2 %0, %1, %2, %0;" : "+l"(acc) : "l"(a), "l"(b));
}
__device__ __forceinline__ unsigned long long ffma2v(unsigned long long a,
                                                     unsigned long long b,
                                                     unsigned long long c) {
    unsigned long long r;
    asm("fma.rn.f32x2 %0, %1, %2, %3;" : "=l"(r) : "l"(a), "l"(b), "l"(c));
    return r;
}
__device__ __forceinline__ unsigned long long fadd2(unsigned long long a,
                                                    unsigned long long b) {
    unsigned long long r;
    asm("add.rn.f32x2 %0, %1, %2;" : "=l"(r) : "l"(a), "l"(b));
    return r;
}
__device__ __forceinline__ unsigned long long packdup(float v) {
    unsigned long long r;
    asm("mov.b64 %0, {%1, %1};" : "=l"(r) : "r"(__float_as_uint(v)));
    return r;
}
__device__ __forceinline__ unsigned s2u(const void* p) {
    return (unsigned)__cvta_generic_to_shared(p);
}
__device__ __forceinline__ void cpasync16(unsigned dst, const void* src) {
    asm volatile("cp.async.cg.shared.global [%0], [%1], 16;"
                 :: "r"(dst), "l"(src));
}

// ---------------------------------------------------------------------------
// 128x128 tiles, 512 threads (R13 skeleton + cp.async + dup-q + packed epi):
//  - tile prefetch via cp.async (no LDG->STS warp stall; wait at tile end)
//  - query tile stored DUPLICATED as f32x2 in smem -> zero packdup in mainloop
//  - compute: 32x16 grid, 4x4 f32x2 fragments; 4 LDS.128 + 16 FFMA2 / c-step
//  - epilogue fully packed: d2 = fma2(acc, -2, rn2) + cn2 (bitwise == scalar)
//  - scan: R13 filter (quarter-row vs row-shared bound) + batch insert,
//    CAP=24 with in-order flush (tile 0 only)
//  - end: 4-way lexicographic (d, idx) merge per row == jax top_k order
// ---------------------------------------------------------------------------
__global__ __launch_bounds__(NTHREADS, 1)
void knn_kernel(const float* __restrict__ x, float* __restrict__ out) {
    extern __shared__ float sm[];
    float* qt2 = sm + SM_QT;    // duplicated pairs, entry (c,r) at c*256+2r
    float* ptb = sm + SM_PT;    // [2][32][128]
    float* dt  = sm + SM_DT;
    float* rn  = sm + SM_RN;
    float* cnb = sm + SM_CN;    // [2][128]
    float* qh  = sm + SM_QH;
    float* bd  = sm + SM_BD;
    short* bi  = (short*)(sm + SM_BI);

    const int b    = blockIdx.y;
    const int row0 = blockIdx.x * TILE;
    const int tid  = threadIdx.x;
    const int tx   = tid & 15;
    const int ty   = tid >> 4;
    const float* xb = x + (size_t)(b * CDIM) * NPTS;

    const int srow = tid >> 2;
    const int sq   = tid & 3;
    const int ssw  = srow & 31;

    float dl[KALL];
    int   il[KALL];
#pragma unroll
    for (int j = 0; j < KALL; j++) { dl[j] = 3.4e38f; il[j] = 0x7FFFFFFF; }

    auto insert = [&](float d, int mi) {
#pragma unroll
        for (int j = KALL - 1; j >= 1; j--) {
            bool sh = d < dl[j - 1];
            bool pl = !sh && (d < dl[j]);
            float pd = dl[j - 1]; int pi = il[j - 1];
            dl[j] = sh ? pd : (pl ? d  : dl[j]);
            il[j] = sh ? pi : (pl ? mi : il[j]);
        }
        if (d < dl[0]) { dl[0] = d; il[0] = mi; }
    };

    // duplicated query tile: qt2[c][r] = (v, v)
#pragma unroll
    for (int k = 0; k < (CDIM * TILE) / NTHREADS; k++) {
        int idx = k * NTHREADS + tid;
        float v = xb[(idx >> 7) * NPTS + row0 + (idx & 127)];
        qt2[2 * idx]     = v;
        qt2[2 * idx + 1] = v;
    }
    if (tid < TILE) rn[tid] = g_sq[b * NPTS + row0 + tid];
    qh[tid] = 3.4e38f;

    // prologue: tile 0 into buffer 0 via cp.async
    {
#pragma unroll
        for (int k = 0; k < 2; k++) {
            int i4 = k * NTHREADS + tid;          // float4 index in [32][32]
            int c = i4 >> 5, c4 = i4 & 31;
            cpasync16(s2u(ptb + c * TILE + 4 * c4),
                      xb + c * NPTS + 4 * c4);
        }
        if (tid < 32)
            cpasync16(s2u(cnb + 4 * tid), g_sq + b * NPTS + 4 * tid);
        asm volatile("cp.async.commit_group;");
        asm volatile("cp.async.wait_group 0;");
    }
    __syncthreads();

    for (int t = 0; t < NPTS / TILE; t++) {
        const int cur = t & 1;
        float* pt = ptb + cur * CDIM * TILE;
        float* cn = cnb + cur * TILE;
        const int m0 = t * TILE;

        // fire-and-forget prefetch of next tile
        if (t < NPTS / TILE - 1) {
            float* ptn = ptb + (cur ^ 1) * CDIM * TILE;
            const int m1 = m0 + TILE;
#pragma unroll
            for (int k = 0; k < 2; k++) {
                int i4 = k * NTHREADS + tid;
                int c = i4 >> 5, c4 = i4 & 31;
                cpasync16(s2u(ptn + c * TILE + 4 * c4),
                          xb + c * NPTS + m1 + 4 * c4);
            }
            if (tid < 32)
                cpasync16(s2u(cnb + (cur ^ 1) * TILE + 4 * tid),
                          g_sq + b * NPTS + m1 + 4 * tid);
            asm volatile("cp.async.commit_group;");
        }

        // ---- 128x128x32 inner products: 4 rows x 4 col-pairs of f32x2 ----
        unsigned long long acc2[4][4];
#pragma unroll
        for (int i = 0; i < 4; i++)
#pragma unroll
            for (int j = 0; j < 4; j++) acc2[i][j] = 0ull;

#pragma unroll 2
        for (int c = 0; c < CDIM; c++) {
            ulonglong2 qA = *(const ulonglong2*)(qt2 + c * 2 * TILE + 8 * ty);
            ulonglong2 qB = *(const ulonglong2*)(qt2 + c * 2 * TILE + 8 * ty + 4);
            ulonglong2 pA = *(const ulonglong2*)(pt + c * TILE + 4 * tx);
            ulonglong2 pB = *(const ulonglong2*)(pt + c * TILE + 64 + 4 * tx);
            unsigned long long qq[4] = {qA.x, qA.y, qB.x, qB.y};
#pragma unroll
            for (int i = 0; i < 4; i++) {
                ffma2(acc2[i][0], qq[i], pA.x);
                ffma2(acc2[i][1], qq[i], pA.y);
                ffma2(acc2[i][2], qq[i], pB.x);
                ffma2(acc2[i][3], qq[i], pB.y);
            }
        }

        // ---- packed epilogue: d2 = fma2(acc,-2,rn2) + cn2, swizzled stores ----
        {
            const unsigned long long NEG2 = 0xC0000000C0000000ull;
            ulonglong2 cnA = *(const ulonglong2*)(cn + 4 * tx);
            ulonglong2 cnB = *(const ulonglong2*)(cn + 64 + 4 * tx);
#pragma unroll
            for (int i = 0; i < 4; i++) {
                int r = 4 * ty + i;
                unsigned long long rn2 = packdup(rn[r]);
                ulonglong2 v0, v1;
                v0.x = fadd2(ffma2v(acc2[i][0], NEG2, rn2), cnA.x);
                v0.y = fadd2(ffma2v(acc2[i][1], NEG2, rn2), cnA.y);
                v1.x = fadd2(ffma2v(acc2[i][2], NEG2, rn2), cnB.x);
                v1.y = fadd2(ffma2v(acc2[i][3], NEG2, rn2), cnB.y);
                int sw = r & 31;
                ulonglong2* dtr = (ulonglong2*)dt + r * 32;
                dtr[tx ^ sw]        = v0;
                dtr[(16 + tx) ^ sw] = v1;
            }
        }
        __syncwarp();   // dt rows for this warp are warp-private

        // ---- phase A: filter quarter-row vs row-shared bound ----
        {
            const float* qhr = qh + srow * 4;
            float tv = fminf(fminf(qhr[0], qhr[1]), fminf(qhr[2], qhr[3]));

            const float4* dtr = (const float4*)dt + srow * 32;
            int cnt = 0;
#pragma unroll
            for (int l = 0; l < 8; l++) {
                float4 v = dtr[(sq * 8 + l) ^ ssw];
                int mb = m0 + sq * 32 + 4 * l;
                float dv[4] = {v.x, v.y, v.z, v.w};
#pragma unroll
                for (int e = 0; e < 4; e++) {
                    float d = dv[e];
                    if (d <= tv) {
                        if (cnt == CAP) {   // in-order flush (tile 0 only)
                            for (int s = 0; s < CAP; s++)
                                insert(bd[s * NTHREADS + tid],
                                       (int)bi[s * NTHREADS + tid]);
                            cnt = 0;
                        }
                        bd[cnt * NTHREADS + tid] = d;
                        bi[cnt * NTHREADS + tid] = (short)(mb + e);
                        cnt++;
                    }
                }
            }

            // ---- phase B: batch insert, warp-max(cnt) network runs ----
            int nmax = __reduce_max_sync(0xFFFFFFFFu, cnt);
            for (int s = 0; s < nmax; s++) {
                float d  = 3.4e38f;
                int   mi = 0x7FFFFFFF;
                if (s < cnt) {
                    d  = bd[s * NTHREADS + tid];
                    mi = (int)bi[s * NTHREADS + tid];
                }
                insert(d, mi);   // +INF lanes are no-ops
            }
            qh[tid] = dl[KALL - 1];   // warp-private publish
        }
        asm volatile("cp.async.wait_group 0;");
        __syncthreads();   // next-buffer loads visible; cur free to overwrite
    }

    // ---- dump quarter lists into dt region, then 4-way merge per row ----
    float* sd = dt;
    short* si = (short*)(dt + NTHREADS * KALL);
#pragma unroll
    for (int j = 0; j < KALL; j++) {
        sd[tid * KALL + j] = dl[j];
        si[tid * KALL + j] = (short)il[j];
    }
    __syncthreads();

    if (tid < TILE) {
        int cur4[4] = {0, 0, 0, 0};
        int n = row0 + tid;
        int base0 = (b * NPTS + n) * KOUT;
        int base1 = ((NB + b) * NPTS + n) * KOUT;
#pragma unroll
        for (int t = 0; t < KALL; t++) {
            float bdv = 3.5e38f;
            int   biv = 0x7FFFFFFF;
            int   bq = 0;
#pragma unroll
            for (int q = 0; q < 4; q++) {
                int c = cur4[q];
                float d2 = sd[(tid * 4 + q) * KALL + c];
                int   i2 = (int)si[(tid * 4 + q) * KALL + c];
                if (d2 < bdv || (d2 == bdv && i2 < biv)) { bdv = d2; biv = i2; bq = q; }
            }
            cur4[bq]++;
            if ((t & 1) == 0) out[base0 + (t >> 1)] = (float)biv;
        }
#pragma unroll
        for (int j = 0; j < KOUT; j++) out[base1 + j] = (float)n;
    }
}

extern "C" void kernel_launch(void* const* d_in, const int* in_sizes, int n_in,
                              void* d_out, int out_size) {
    const float* x = (const float*)d_in[0];
    float* out = (float*)d_out;

    cudaFuncSetAttribute(knn_kernel, cudaFuncAttributeMaxDynamicSharedMemorySize,
                         SMEM_BYTES);

    sqnorm_kernel<<<(NB * NPTS + 511) / 512, 512>>>(x);

    dim3 grid(NPTS / TILE, NB);
    knn_kernel<<<grid, NTHREADS, SMEM_BYTES>>>(x, out);
}

// round 17
// speedup vs baseline: 1.4153x; 1.0735x over previous
#include <cuda_runtime.h>

#define NPTS  4096
#define NB    8
#define CDIM  32
#define KOUT  9
#define KALL  18
#define TILE  128
#define NTHREADS 512
#define CAP   32

// shared memory layout (float offsets)
#define SM_QT 0
#define SM_PT (SM_QT + CDIM*TILE)            // 4096   pt[2][32][128]
#define SM_DT (SM_PT + 2*CDIM*TILE)          // 12288
#define SM_RN (SM_DT + TILE*TILE)            // 28672
#define SM_CN (SM_RN + TILE)                 // 28800  cn[2][128]
#define SM_QH (SM_CN + 2*TILE)               // 29056
#define SM_BD (SM_QH + NTHREADS)             // 29568
#define SM_BI (SM_BD + CAP*NTHREADS)         // 45952
#define SMEM_FLOATS (SM_BI + (CAP*NTHREADS)/2)   // 54144
#define SMEM_BYTES  (SMEM_FLOATS * 4)        // 216,576 bytes

__device__ float g_sq[NB * NPTS];

__global__ void sqnorm_kernel(const float* __restrict__ x) {
    int idx = blockIdx.x * blockDim.x + threadIdx.x;
    if (idx >= NB * NPTS) return;
    int b = idx >> 12;
    int n = idx & (NPTS - 1);
    const float* p = x + (size_t)(b * CDIM) * NPTS + n;
    float s = 0.f;
#pragma unroll
    for (int c = 0; c < CDIM; c++) {
        float v = p[c * NPTS];
        s = fmaf(v, v, s);
    }
    g_sq[idx] = s;
}

__device__ __forceinline__ void ffma2(unsigned long long& acc,
                                      unsigned long long a,
                                      unsigned long long b) {
    asm("fma.rn.f32x2 %0, %1, %2, %0;" : "+l"(acc) : "l"(a), "l"(b));
}
__device__ __forceinline__ unsigned long long packdup(float v) {
    unsigned long long r;
    asm("mov.b64 %0, {%1, %1};" : "=l"(r) : "r"(__float_as_uint(v)));
    return r;
}
__device__ __forceinline__ void unpack2(unsigned long long v, float& lo, float& hi) {
    unsigned int a, b;
    asm("mov.b64 {%0, %1}, %2;" : "=r"(a), "=r"(b) : "l"(v));
    lo = __uint_as_float(a); hi = __uint_as_float(b);
}
__device__ __forceinline__ unsigned s2u(const void* p) {
    return (unsigned)__cvta_generic_to_shared(p);
}
__device__ __forceinline__ void cpasync16(unsigned dst, const void* src) {
    asm volatile("cp.async.cg.shared.global [%0], [%1], 16;"
                 :: "r"(dst), "l"(src));
}

// ---------------------------------------------------------------------------
// R13 skeleton (450us) + cp.async prefetch ONLY:
//  - compute: 32x16 grid, 4x4 f32x2 fragments (fma.rn.f32x2, bit-identical
//    per lane to scalar fmaf)
//  - tile prefetch via cp.async: no LDG->STS synchronized warp stall at the
//    top of each tile; wait_group 0 only at the tile boundary
//  - warp w writes AND scans dt rows 8w..8w+7 -> __syncwarp only; qh
//    warp-private
//  - scan: filter vs row-shared bound -> lane-private push (CAP=32), batch
//    insert warp-max(cnt) network runs (+INF lanes no-op)
//  - end: 4-way lexicographic (d, idx) merge per row == jax top_k order
// ---------------------------------------------------------------------------
__global__ __launch_bounds__(NTHREADS, 1)
void knn_kernel(const float* __restrict__ x, float* __restrict__ out) {
    extern __shared__ float sm[];
    float* qt = sm + SM_QT;
    float* ptb = sm + SM_PT;   // [2][32][128]
    float* dt = sm + SM_DT;
    float* rn = sm + SM_RN;
    float* cnb = sm + SM_CN;   // [2][128]
    float* qh = sm + SM_QH;
    float* bd = sm + SM_BD;
    short* bi = (short*)(sm + SM_BI);

    const int b    = blockIdx.y;
    const int row0 = blockIdx.x * TILE;
    const int tid  = threadIdx.x;
    const int tx   = tid & 15;
    const int ty   = tid >> 4;
    const float* xb = x + (size_t)(b * CDIM) * NPTS;

    const int srow = tid >> 2;
    const int sq   = tid & 3;
    const int ssw  = srow & 31;

    float dl[KALL];
    int   il[KALL];
#pragma unroll
    for (int j = 0; j < KALL; j++) { dl[j] = 3.4e38f; il[j] = 0x7FFFFFFF; }

#pragma unroll
    for (int k = 0; k < (CDIM * TILE) / NTHREADS; k++) {
        int idx = k * NTHREADS + tid;
        qt[idx] = xb[(idx >> 7) * NPTS + row0 + (idx & 127)];
    }
    if (tid < TILE) rn[tid] = g_sq[b * NPTS + row0 + tid];
    qh[tid] = 3.4e38f;
    // prologue: tile 0 into buffer 0 via cp.async
#pragma unroll
    for (int k = 0; k < 2; k++) {
        int i4 = k * NTHREADS + tid;              // float4 index in [32][32]
        int c = i4 >> 5, c4 = i4 & 31;
        cpasync16(s2u(ptb + c * TILE + 4 * c4), xb + c * NPTS + 4 * c4);
    }
    if (tid < 32) cpasync16(s2u(cnb + 4 * tid), g_sq + b * NPTS + 4 * tid);
    asm volatile("cp.async.commit_group;");
    asm volatile("cp.async.wait_group 0;");
    __syncthreads();

    for (int t = 0; t < NPTS / TILE; t++) {
        const int cur = t & 1;
        float* pt = ptb + cur * CDIM * TILE;
        float* cn = cnb + cur * TILE;
        const int m0 = t * TILE;

        // fire-and-forget prefetch of next tile
        if (t < NPTS / TILE - 1) {
            float* ptn = ptb + (cur ^ 1) * CDIM * TILE;
            const int m1 = m0 + TILE;
#pragma unroll
            for (int k = 0; k < 2; k++) {
                int i4 = k * NTHREADS + tid;
                int c = i4 >> 5, c4 = i4 & 31;
                cpasync16(s2u(ptn + c * TILE + 4 * c4),
                          xb + c * NPTS + m1 + 4 * c4);
            }
            if (tid < 32)
                cpasync16(s2u(cnb + (cur ^ 1) * TILE + 4 * tid),
                          g_sq + b * NPTS + m1 + 4 * tid);
            asm volatile("cp.async.commit_group;");
        }

        // ---- 128x128x32 inner products: 4 rows x 4 col-pairs of f32x2 ----
        unsigned long long acc2[4][4];
#pragma unroll
        for (int i = 0; i < 4; i++)
#pragma unroll
            for (int j = 0; j < 4; j++) acc2[i][j] = 0ull;

#pragma unroll 2
        for (int c = 0; c < CDIM; c++) {
            float4 q = *(const float4*)(qt + c * TILE + 4 * ty);
            ulonglong2 pA = *(const ulonglong2*)(pt + c * TILE + 4 * tx);
            ulonglong2 pB = *(const ulonglong2*)(pt + c * TILE + 64 + 4 * tx);
            unsigned long long qq[4] = {packdup(q.x), packdup(q.y),
                                        packdup(q.z), packdup(q.w)};
#pragma unroll
            for (int i = 0; i < 4; i++) {
                ffma2(acc2[i][0], qq[i], pA.x);
                ffma2(acc2[i][1], qq[i], pA.y);
                ffma2(acc2[i][2], qq[i], pB.x);
                ffma2(acc2[i][3], qq[i], pB.y);
            }
        }

        // ---- epilogue: d = (rn - 2*acc) + cn, swizzled float4 stores ----
        float cnv[8];
#pragma unroll
        for (int j = 0; j < 8; j++)
            cnv[j] = cn[(j < 4) ? (4 * tx + j) : (60 + 4 * tx + j)];

#pragma unroll
        for (int i = 0; i < 4; i++) {
            int r = 4 * ty + i;
            float rni = rn[r];
            float a0, a1, a2, a3, a4, a5, a6, a7;
            unpack2(acc2[i][0], a0, a1);
            unpack2(acc2[i][1], a2, a3);
            unpack2(acc2[i][2], a4, a5);
            unpack2(acc2[i][3], a6, a7);
            float4 v0, v1;
            v0.x = (rni - 2.f * a0) + cnv[0];
            v0.y = (rni - 2.f * a1) + cnv[1];
            v0.z = (rni - 2.f * a2) + cnv[2];
            v0.w = (rni - 2.f * a3) + cnv[3];
            v1.x = (rni - 2.f * a4) + cnv[4];
            v1.y = (rni - 2.f * a5) + cnv[5];
            v1.z = (rni - 2.f * a6) + cnv[6];
            v1.w = (rni - 2.f * a7) + cnv[7];
            int sw = r & 31;
            float4* dtr = (float4*)dt + r * 32;
            dtr[tx ^ sw]        = v0;
            dtr[(16 + tx) ^ sw] = v1;
        }
        __syncwarp();   // dt rows for this warp are warp-private

        // ---- phase A: filter quarter-row vs row-shared bound ----
        {
            const float* qhr = qh + srow * 4;
            float tv = fminf(fminf(qhr[0], qhr[1]), fminf(qhr[2], qhr[3]));

            const float4* dtr = (const float4*)dt + srow * 32;
            int cnt = 0;
#pragma unroll
            for (int l = 0; l < 8; l++) {
                float4 v = dtr[(sq * 8 + l) ^ ssw];
                int mb = m0 + sq * 32 + 4 * l;
                float dv[4] = {v.x, v.y, v.z, v.w};
#pragma unroll
                for (int e = 0; e < 4; e++) {
                    float d = dv[e];
                    if (d <= tv) {
                        bd[cnt * NTHREADS + tid] = d;
                        bi[cnt * NTHREADS + tid] = (short)(mb + e);
                        cnt++;
                    }
                }
            }

            // ---- phase B: batch insert, warp-max(cnt) network runs ----
            int nmax = __reduce_max_sync(0xFFFFFFFFu, cnt);
            for (int s = 0; s < nmax; s++) {
                float d  = 3.4e38f;
                int   mi = 0x7FFFFFFF;
                if (s < cnt) {
                    d  = bd[s * NTHREADS + tid];
                    mi = (int)bi[s * NTHREADS + tid];
                }
                // branch-free sorted insert; +INF lanes are no-ops
#pragma unroll
                for (int j = KALL - 1; j >= 1; j--) {
                    bool sh = d < dl[j - 1];
                    bool pl = !sh && (d < dl[j]);
                    float pd = dl[j - 1]; int pi = il[j - 1];
                    dl[j] = sh ? pd : (pl ? d  : dl[j]);
                    il[j] = sh ? pi : (pl ? mi : il[j]);
                }
                if (d < dl[0]) { dl[0] = d; il[0] = mi; }
            }
            qh[tid] = dl[KALL - 1];   // warp-private publish
        }
        asm volatile("cp.async.wait_group 0;");
        __syncthreads();   // next-buffer loads visible; cur free to overwrite
    }

    // ---- dump quarter lists into dt region, then 4-way merge per row ----
    float* sd = dt;
    short* si = (short*)(dt + NTHREADS * KALL);
#pragma unroll
    for (int j = 0; j < KALL; j++) {
        sd[tid * KALL + j] = dl[j];
        si[tid * KALL + j] = (short)il[j];
    }
    __syncthreads();

    if (tid < TILE) {
        int cur4[4] = {0, 0, 0, 0};
        int n = row0 + tid;
        int base0 = (b * NPTS + n) * KOUT;
        int base1 = ((NB + b) * NPTS + n) * KOUT;
#pragma unroll
        for (int t = 0; t < KALL; t++) {
            float bdv = 3.5e38f;
            int   biv = 0x7FFFFFFF;
            int   bq = 0;
#pragma unroll
            for (int q = 0; q < 4; q++) {
                int c = cur4[q];
                float d2 = sd[(tid * 4 + q) * KALL + c];
                int   i2 = (int)si[(tid * 4 + q) * KALL + c];
                if (d2 < bdv || (d2 == bdv && i2 < biv)) { bdv = d2; biv = i2; bq = q; }
            }
            cur4[bq]++;
            if ((t & 1) == 0) out[base0 + (t >> 1)] = (float)biv;
        }
#pragma unroll
        for (int j = 0; j < KOUT; j++) out[base1 + j] = (float)n;
    }
}

extern "C" void kernel_launch(void* const* d_in, const int* in_sizes, int n_in,
                              void* d_out, int out_size) {
    const float* x = (const float*)d_in[0];
    float* out = (float*)d_out;

    cudaFuncSetAttribute(knn_kernel, cudaFuncAttributeMaxDynamicSharedMemorySize,
                         SMEM_BYTES);

    sqnorm_kernel<<<(NB * NPTS + 511) / 512, 512>>>(x);

    dim3 grid(NPTS / TILE, NB);
    knn_kernel<<<grid, NTHREADS, SMEM_BYTES>>>(x, out);
}